// round 10
// baseline (speedup 1.0000x reference)
#include <cuda_runtime.h>
#include <cuda_fp16.h>
#include <cstdint>
#include <cstddef>

// ScaledDotProductAttention B=16, S=2048, D=128 fp32 (sm_100 classic mma.sync).
// Out = context [16,2048,128] ++ attention [16,2048,2048].
//
// Round 10: warp-specialized two-pass kernel, 512 threads/CTA.
//  Pass 1 (row sums): warp-groups split the KEY range (A: keys 0-1023,
//    B: 1024-2047), each 16 K-only stages on its own 2-buffer ring with
//    group-scoped bar.sync; l = lA + lB via smem. S bits identical to pass 2.
//  Pass 2 (pipelined): producers (warps 0-7) do QK (Q LDSM'd from smem),
//    exp*rinv, normalized attention STG, P(x64,fp16)->smem; consumers
//    (warps 8-15) do PV from P/V LDSM and own the O accumulator, writing
//    context = O/64. Producer(s) overlaps consumer(s-1) between barriers.
//  cvt_kv : K -> fp16 [b][key][d]; V -> fp16 transposed pair-words.

#define BATCH 16
#define SEQ   2048
#define DIM   128

#define KSTR  68                 // words per K row (64+4)
#define VSTR2 36                 // words per V d-row (32+4)
#define PSTR  36                 // words per P row (32+4)
#define KBUF (64*KSTR)           // 4352
#define VBUF (128*VSTR2)         // 4608
#define STAGE_W (KBUF + VBUF)    // 8960
#define NBUF 4
#define PW   (NBUF*STAGE_W)      // 35840 : P double buffer
#define PBUF (128*PSTR)          // 4608
#define QSW  (PW + 2*PBUF)       // 45056 : Q fp16 tile (128 x 68 words)
#define LSW  (QSW + 128*68)      // 53760 : lsumA[128], lsumB[128]
#define SMEM_WORDS (LSW + 256)   // 54016 words = 216,064 B

__device__ __half   g_kh[BATCH * SEQ * DIM];
__device__ uint32_t g_vh[BATCH * DIM * (SEQ / 2)];   // [b][d][pair]

__device__ __forceinline__ uint32_t smem_u32(const void* p) {
    uint32_t a;
    asm("{ .reg .u64 t; cvta.to.shared.u64 t, %1; cvt.u32.u64 %0, t; }" : "=r"(a) : "l"(p));
    return a;
}
__device__ __forceinline__ float ex2(float x) {
    float y; asm("ex2.approx.f32 %0, %1;" : "=f"(y) : "f"(x)); return y;
}
__device__ __forceinline__ uint32_t h2(float a, float b) {
    uint32_t r;
    asm("cvt.rn.f16x2.f32 %0, %2, %1;" : "=r"(r) : "f"(a), "f"(b));
    return r;
}
__device__ __forceinline__ void mma_f16(float& c0, float& c1, float& c2, float& c3,
                                        uint32_t a0, uint32_t a1, uint32_t a2, uint32_t a3,
                                        uint32_t b0, uint32_t b1) {
    asm("mma.sync.aligned.m16n8k16.row.col.f32.f16.f16.f32 "
        "{%0,%1,%2,%3}, {%4,%5,%6,%7}, {%8,%9}, {%0,%1,%2,%3};"
        : "+f"(c0), "+f"(c1), "+f"(c2), "+f"(c3)
        : "r"(a0), "r"(a1), "r"(a2), "r"(a3), "r"(b0), "r"(b1));
}
__device__ __forceinline__ void ldsm4(uint32_t& r0, uint32_t& r1, uint32_t& r2,
                                      uint32_t& r3, uint32_t addr) {
    asm volatile("ldmatrix.sync.aligned.m8n8.x4.shared.b16 {%0,%1,%2,%3}, [%4];"
                 : "=r"(r0), "=r"(r1), "=r"(r2), "=r"(r3) : "r"(addr));
}

#define CP16(dst, src) \
    asm volatile("cp.async.cg.shared.global [%0], [%1], 16;" :: "r"(dst), "l"(src))
#define CP_COMMIT() asm volatile("cp.async.commit_group;" ::: "memory")
#define CP_WAIT(n)  asm volatile("cp.async.wait_group %0;" :: "n"(n) : "memory")
#define BARG(id)    asm volatile("bar.sync %0, 256;" :: "r"(id) : "memory")

// K-only stage fill by one 256-thread group
__device__ __forceinline__ void issue_k_grp(uint32_t smb, const __half* kh,
                                            int s, int buf, int t256) {
    const uint32_t base = smb + (uint32_t)(buf * STAGE_W) * 4;
    const char* kp = (const char*)(kh + (size_t)s * 64 * DIM);
#pragma unroll
    for (int j = 0; j < 4; j++) {
        int i = t256 + j * 256;
        int kr = i >> 4, kc = i & 15;
        CP16(base + (uint32_t)(kr * KSTR * 4 + kc * 16), kp + kr * 256 + kc * 16);
    }
    CP_COMMIT();
}

// full stage fill by all 512 threads
__device__ __forceinline__ void issue_stage512(uint32_t smb, const __half* kh,
                                               const uint32_t* vh, int s, int tid) {
    const uint32_t base = smb + (uint32_t)((s & 3) * STAGE_W) * 4;
    const char* kp = (const char*)(kh + (size_t)s * 64 * DIM);
    const char* vp = (const char*)(vh + (size_t)s * 32);
#pragma unroll
    for (int j = 0; j < 2; j++) {
        int i = tid + j * 512;
        int kr = i >> 4, kc = i & 15;
        CP16(base + (uint32_t)(kr * KSTR * 4 + kc * 16), kp + kr * 256 + kc * 16);
        int vr = i >> 3, vc = i & 7;
        CP16(base + (uint32_t)(KBUF * 4 + vr * VSTR2 * 4 + vc * 16),
             vp + (size_t)vr * (SEQ / 2) * 4 + vc * 16);
    }
    CP_COMMIT();
}

// K -> fp16 elementwise; V -> fp16 transposed pair-words via smem tile.
__global__ void __launch_bounds__(256)
cvt_kv(const float* __restrict__ k, const float* __restrict__ v) {
    const int tid = threadIdx.x;
    const size_t nkw = (size_t)BATCH * SEQ * DIM / 2;
    for (size_t w = (size_t)blockIdx.x * 256 + tid; w < nkw; w += (size_t)gridDim.x * 256) {
        float2 kf = ((const float2*)k)[w];
        ((uint32_t*)g_kh)[w] = h2(kf.x, kf.y);
    }
    __shared__ float s[64][33];
    const int bx = blockIdx.x;
    const int b  = bx >> 7;
    const int pt = (bx >> 2) & 31;
    const int dt = bx & 3;
    const float* vb = v + ((size_t)b * SEQ + pt * 64) * DIM + dt * 32;
#pragma unroll
    for (int j = 0; j < 8; j++) {
        int i = tid + j * 256;
        int kk = i >> 5, dd = i & 31;
        s[kk][dd] = vb[(size_t)kk * DIM + dd];
    }
    __syncthreads();
    uint32_t* dst = g_vh + (size_t)b * DIM * (SEQ / 2) + (size_t)(dt * 32) * (SEQ / 2) + pt * 32;
#pragma unroll
    for (int j = 0; j < 4; j++) {
        int i = tid + j * 256;
        int pp = i & 31, dd = i >> 5;
        dst[(size_t)dd * (SEQ / 2) + pp] = h2(s[2 * pp][dd], s[2 * pp + 1][dd]);
    }
}

__global__ void __launch_bounds__(512, 1)
attn1(const float* __restrict__ qg_, float* __restrict__ out) {
    extern __shared__ float sm[];
    const uint32_t smb = smem_u32(sm);

    const int tid = threadIdx.x;
    const int warp = tid >> 5, lane = tid & 31;
    const int g = lane >> 2, qq = lane & 3;
    const bool prod = (warp < 8);
    const int wg = prod ? warp : (warp - 8);
    const int row0 = wg * 16 + g;
    const int t256 = tid & 255;

    const int b = blockIdx.y, qb = blockIdx.x;
    const float* qg = qg_ + ((size_t)b * SEQ + (size_t)qb * 128) * DIM;
    const __half* kh = g_kh + (size_t)b * SEQ * DIM;
    const uint32_t* vh = g_vh + (size_t)b * DIM * (SEQ / 2);
    float* ctx = out + ((size_t)b * SEQ + (size_t)qb * 128) * DIM;
    float* att = out + (size_t)BATCH * SEQ * DIM
                     + ((size_t)b * SEQ + (size_t)qb * 128) * SEQ;

    // pass-1 group config: A = producers (keys 0-1023, bufs 0/1, bar 1),
    //                      B = consumers (keys 1024-2047, bufs 2/3, bar 2)
    const int t0  = prod ? 0 : 16;
    const int bb  = prod ? 0 : 2;
    const int gid = prod ? 1 : 2;
    issue_k_grp(smb, kh, t0, bb, t256);

    // ---- Q -> smem fp16 tile (qsc folded); used by pass-2 producers ----
    const float qsc = 0.088388347648318447f * 1.4426950408889634f;
    for (int i = tid; i < 4096; i += 512) {
        int r = i >> 5, c = i & 31;
        float4 f = *(const float4*)(qg + (size_t)r * DIM + c * 4);
        uint32_t* qs = (uint32_t*)sm + QSW + r * 68 + c * 2;
        qs[0] = h2(f.x * qsc, f.y * qsc);
        qs[1] = h2(f.z * qsc, f.w * qsc);
    }

    // ---- Q A-frags in registers for pass 1 (dead after; reused for O) ----
    const float* q0 = qg + (size_t)row0 * DIM;
    const float* q1 = q0 + 8 * DIM;
    uint32_t qa[8][4];
#pragma unroll
    for (int t = 0; t < 8; t++) {
        int c0 = 16 * t + 2 * qq;
        qa[t][0] = h2(q0[c0] * qsc,     q0[c0 + 1] * qsc);
        qa[t][1] = h2(q1[c0] * qsc,     q1[c0 + 1] * qsc);
        qa[t][2] = h2(q0[c0 + 8] * qsc, q0[c0 + 9] * qsc);
        qa[t][3] = h2(q1[c0 + 8] * qsc, q1[c0 + 9] * qsc);
    }

    const uint32_t kln = (uint32_t)((lane & 7) * KSTR * 4 + 16 * (lane >> 3));
    const uint32_t vln = (uint32_t)((lane & 7) * VSTR2 * 4 + ((lane >> 3) & 1) * 16
                                    + (lane >> 4) * 8 * VSTR2 * 4);
    const uint32_t qln = (uint32_t)(QSW * 4 + (16 * wg + (lane & 15)) * KSTR * 4
                                    + (lane >> 4) * 16);
    const uint32_t plnC = (uint32_t)((16 * wg + (lane & 15)) * PSTR * 4
                                     + (lane >> 4) * 16);

    // ================= PASS 1: row sums, keys split across groups ==========
    float l0 = 0.f, l1 = 0.f;
    for (int t = 0; t < 16; ++t) {
        CP_WAIT(0);
        BARG(gid);
        if (t < 15) issue_k_grp(smb, kh, t0 + t + 1, bb + ((t + 1) & 1), t256);
        const uint32_t kbase = smb + (uint32_t)((bb + (t & 1)) * STAGE_W) * 4 + kln;

        float cf[8][4];
#pragma unroll
        for (int i = 0; i < 8; i++) { cf[i][0] = cf[i][1] = cf[i][2] = cf[i][3] = 0.f; }
#pragma unroll
        for (int u = 0; u < 4; u++) {
#pragma unroll
            for (int nt = 0; nt < 8; nt++) {
                uint32_t b00, b01, b10, b11;
                ldsm4(b00, b01, b10, b11, kbase + (uint32_t)(nt * 8 * KSTR * 4 + u * 64));
                mma_f16(cf[nt][0], cf[nt][1], cf[nt][2], cf[nt][3],
                        qa[2*u][0], qa[2*u][1], qa[2*u][2], qa[2*u][3], b00, b01);
                mma_f16(cf[nt][0], cf[nt][1], cf[nt][2], cf[nt][3],
                        qa[2*u+1][0], qa[2*u+1][1], qa[2*u+1][2], qa[2*u+1][3], b10, b11);
            }
        }
#pragma unroll
        for (int nt = 0; nt < 8; nt++) {
            l0 += ex2(cf[nt][0]) + ex2(cf[nt][1]);
            l1 += ex2(cf[nt][2]) + ex2(cf[nt][3]);
        }
    }
    l0 += __shfl_xor_sync(0xffffffffu, l0, 1);
    l0 += __shfl_xor_sync(0xffffffffu, l0, 2);
    l1 += __shfl_xor_sync(0xffffffffu, l1, 1);
    l1 += __shfl_xor_sync(0xffffffffu, l1, 2);
    if (qq == 0) {
        int base = LSW + (prod ? 0 : 128);
        sm[base + row0]     = l0;
        sm[base + row0 + 8] = l1;
    }
    __syncthreads();     // lsums visible; all pass-1 buffer reads finished

    float r0 = 0.f, r1 = 0.f;
    if (prod) {
        r0 = 1.0f / (sm[LSW + row0]     + sm[LSW + 128 + row0]);
        r1 = 1.0f / (sm[LSW + row0 + 8] + sm[LSW + 128 + row0 + 8]);
    }

    // ================= PASS 2: producer/consumer pipeline ==================
    issue_stage512(smb, kh, vh, 0, tid);
    issue_stage512(smb, kh, vh, 1, tid);

    float o[16][4];
#pragma unroll
    for (int i = 0; i < 16; i++) { o[i][0] = o[i][1] = o[i][2] = o[i][3] = 0.f; }

    for (int s = 0; s < 33; ++s) {
        if (s < 31) { CP_WAIT(1); } else if (s == 31) { CP_WAIT(0); }
        __syncthreads();     // P(s-1) visible; K/V(s) ready; P(s-2) readers done
        if (s < 30) issue_stage512(smb, kh, vh, s + 2, tid);

        if (prod) {
            if (s < 32) {
                const uint32_t kbase = smb + (uint32_t)((s & 3) * STAGE_W) * 4 + kln;
                const uint32_t qbase = smb + qln;

                float cf[8][4];
#pragma unroll
                for (int i = 0; i < 8; i++) { cf[i][0] = cf[i][1] = cf[i][2] = cf[i][3] = 0.f; }
#pragma unroll
                for (int u = 0; u < 4; u++) {
                    uint32_t x0, x1, x2, x3, y0, y1, y2, y3;
                    ldsm4(x0, x1, x2, x3, qbase + (uint32_t)(u * 64));
                    ldsm4(y0, y1, y2, y3, qbase + (uint32_t)(u * 64 + 32));
#pragma unroll
                    for (int nt = 0; nt < 8; nt++) {
                        uint32_t b00, b01, b10, b11;
                        ldsm4(b00, b01, b10, b11, kbase + (uint32_t)(nt * 8 * KSTR * 4 + u * 64));
                        mma_f16(cf[nt][0], cf[nt][1], cf[nt][2], cf[nt][3],
                                x0, x1, x2, x3, b00, b01);
                        mma_f16(cf[nt][0], cf[nt][1], cf[nt][2], cf[nt][3],
                                y0, y1, y2, y3, b10, b11);
                    }
                }

                // exp * rinv -> final attention; P*64 -> smem (fp16)
                float* a0p = att + (size_t)row0 * SEQ + 64 * s + 2 * qq;
                float* a1p = a0p + (size_t)8 * SEQ;
                uint32_t* pr0 = (uint32_t*)sm + PW + (s & 1) * PBUF + row0 * PSTR + qq;
                uint32_t* pr1 = pr0 + 8 * PSTR;
#pragma unroll
                for (int nt = 0; nt < 8; nt++) {
                    float p0 = ex2(cf[nt][0]) * r0;
                    float p1 = ex2(cf[nt][1]) * r0;
                    float p2 = ex2(cf[nt][2]) * r1;
                    float p3 = ex2(cf[nt][3]) * r1;
                    *(float2*)(a0p + 8 * nt) = make_float2(p0, p1);
                    *(float2*)(a1p + 8 * nt) = make_float2(p2, p3);
                    pr0[4 * nt] = h2(p0 * 64.0f, p1 * 64.0f);
                    pr1[4 * nt] = h2(p2 * 64.0f, p3 * 64.0f);
                }
            }
        } else {
            if (s >= 1) {
                const int sp = s - 1;
                const uint32_t vbase = smb + (uint32_t)(((sp & 3) * STAGE_W + KBUF)) * 4 + vln;
                const uint32_t pbase = smb + (uint32_t)((PW + (sp & 1) * PBUF) * 4) + plnC;
#pragma unroll
                for (int tt = 0; tt < 4; tt++) {
                    uint32_t A0, A1, A2, A3;
                    ldsm4(A0, A1, A2, A3, pbase + (uint32_t)(tt * 32));
#pragma unroll
                    for (int ndp = 0; ndp < 8; ndp++) {
                        uint32_t v00, v01, v10, v11;
                        ldsm4(v00, v01, v10, v11,
                              vbase + (uint32_t)(tt * 32 + ndp * 16 * VSTR2 * 4));
                        mma_f16(o[2*ndp][0], o[2*ndp][1], o[2*ndp][2], o[2*ndp][3],
                                A0, A1, A2, A3, v00, v01);
                        mma_f16(o[2*ndp+1][0], o[2*ndp+1][1], o[2*ndp+1][2], o[2*ndp+1][3],
                                A0, A1, A2, A3, v10, v11);
                    }
                }
            }
        }
    }

    // ---- context = O / 64 (consumers) ----
    if (!prod) {
        const float inv64 = 0.015625f;
        float* c0p = ctx + (size_t)row0 * DIM + 2 * qq;
        float* c1p = c0p + (size_t)8 * DIM;
#pragma unroll
        for (int nd = 0; nd < 16; nd++) {
            *(float2*)(c0p + 8 * nd) = make_float2(o[nd][0] * inv64, o[nd][1] * inv64);
            *(float2*)(c1p + 8 * nd) = make_float2(o[nd][2] * inv64, o[nd][3] * inv64);
        }
    }
}

__global__ void _noop() {}

extern "C" void kernel_launch(void* const* d_in, const int* in_sizes, int n_in,
                              void* d_out, int out_size) {
    const float* q = (const float*)d_in[0];
    const float* k = (const float*)d_in[1];
    const float* v = (const float*)d_in[2];
    float* out = (float*)d_out;

    cudaFuncSetAttribute(attn1, cudaFuncAttributeMaxDynamicSharedMemorySize,
                         SMEM_WORDS * 4);

    cvt_kv<<<2048, 256>>>(k, v);

    // keep the 4th launch = attn1 (ncu profile position)
    _noop<<<1, 32>>>();
    _noop<<<1, 32>>>();

    dim3 grid(SEQ / 128, BATCH);
    attn1<<<grid, 512, SMEM_WORDS * 4>>>(q, out);
}

// round 11
// speedup vs baseline: 1.1721x; 1.1721x over previous
#include <cuda_runtime.h>
#include <cuda_fp16.h>
#include <cstdint>
#include <cstddef>

// ScaledDotProductAttention B=16, S=2048, D=128 fp32 (sm_100 classic mma.sync).
// Out = context [16,2048,128] ++ attention [16,2048,2048].
//
// Round 11 = round-9 two-pass recompute normalization, with pass 1 fattened:
//  Pass 1: row sums via K-only QK; 128-key GROUPS on a 3-slot ring (one
//          __syncthreads per 128 keys instead of per 64), bigger cp.async
//          batches. Summation order identical to round 9 -> same l bits.
//  Pass 2: (unchanged round-9/6 core) recompute S, store NORMALIZED attention
//          once, P packed x64 to fp16 A-frags in registers, O += P V,
//          context = O/64. 256 threads, 8 warps x 16 q-rows, LDSM everywhere.
//  cvt_kv : K -> fp16 [b][key][d]; V -> fp16 transposed pair-words.

#define BATCH 16
#define SEQ   2048
#define DIM   128

#define KSTR  68                 // words per K row (64+4)
#define VSTR2 36                 // words per V d-row (32+4)
#define KBUF (64*KSTR)           // 4352
#define VBUF (128*VSTR2)         // 4608
#define STAGE_W (KBUF + VBUF)    // 8960
#define NBUF 4
#define SMEM_WORDS (NBUF * STAGE_W)   // 35840 words = 143,360 B
// pass-1 ring: 3 slots x 2*KBUF = 26112 words, aliases the same region

__device__ __half   g_kh[BATCH * SEQ * DIM];
__device__ uint32_t g_vh[BATCH * DIM * (SEQ / 2)];   // [b][d][pair]

__device__ __forceinline__ uint32_t smem_u32(const void* p) {
    uint32_t a;
    asm("{ .reg .u64 t; cvta.to.shared.u64 t, %1; cvt.u32.u64 %0, t; }" : "=r"(a) : "l"(p));
    return a;
}
__device__ __forceinline__ float ex2(float x) {
    float y; asm("ex2.approx.f32 %0, %1;" : "=f"(y) : "f"(x)); return y;
}
__device__ __forceinline__ uint32_t h2(float a, float b) {
    uint32_t r;
    asm("cvt.rn.f16x2.f32 %0, %2, %1;" : "=r"(r) : "f"(a), "f"(b));
    return r;
}
__device__ __forceinline__ void mma_f16(float& c0, float& c1, float& c2, float& c3,
                                        uint32_t a0, uint32_t a1, uint32_t a2, uint32_t a3,
                                        uint32_t b0, uint32_t b1) {
    asm("mma.sync.aligned.m16n8k16.row.col.f32.f16.f16.f32 "
        "{%0,%1,%2,%3}, {%4,%5,%6,%7}, {%8,%9}, {%0,%1,%2,%3};"
        : "+f"(c0), "+f"(c1), "+f"(c2), "+f"(c3)
        : "r"(a0), "r"(a1), "r"(a2), "r"(a3), "r"(b0), "r"(b1));
}
__device__ __forceinline__ void ldsm4(uint32_t& r0, uint32_t& r1, uint32_t& r2,
                                      uint32_t& r3, uint32_t addr) {
    asm volatile("ldmatrix.sync.aligned.m8n8.x4.shared.b16 {%0,%1,%2,%3}, [%4];"
                 : "=r"(r0), "=r"(r1), "=r"(r2), "=r"(r3) : "r"(addr));
}

#define CP16(dst, src) \
    asm volatile("cp.async.cg.shared.global [%0], [%1], 16;" :: "r"(dst), "l"(src))
#define CP_COMMIT() asm volatile("cp.async.commit_group;" ::: "memory")
#define CP_WAIT(n)  asm volatile("cp.async.wait_group %0;" :: "n"(n) : "memory")

// pass-1 group fill: 128 keys (32KB) into slot grp%3. 256 threads.
__device__ __forceinline__ void issue_k_grp128(uint32_t smb, const __half* kh,
                                               int grp, int tid) {
    const uint32_t base = smb + (uint32_t)((grp % 3) * 2 * KBUF) * 4;
    const char* kp = (const char*)(kh + (size_t)grp * 128 * DIM);
#pragma unroll
    for (int j = 0; j < 8; j++) {
        int i = tid + j * 256;                 // 0..2047
        int kr = i >> 4, kc = i & 15;          // 128 rows x 16 chunks
        uint32_t off = (uint32_t)(((kr >> 6) * KBUF + (kr & 63) * KSTR) * 4 + kc * 16);
        CP16(base + off, kp + kr * 256 + kc * 16);
    }
    CP_COMMIT();
}

// pass-2 full stage: K 64 rows + V 128 d-rows slice. 256 threads.
__device__ __forceinline__ void issue_stage(uint32_t smb, const __half* kh,
                                            const uint32_t* vh, int s, int tid) {
    const uint32_t base = smb + (uint32_t)((s & (NBUF - 1)) * STAGE_W) * 4;
    const char* kp = (const char*)(kh + (size_t)s * 64 * DIM);
    const char* vp = (const char*)(vh + (size_t)s * 32);
#pragma unroll
    for (int j = 0; j < 4; j++) {
        int i = tid + j * 256;
        int kr = i >> 4, kc = i & 15;
        CP16(base + (uint32_t)(kr * KSTR * 4 + kc * 16), kp + kr * 256 + kc * 16);
        int vr = i >> 3, vc = i & 7;
        CP16(base + (uint32_t)(KBUF * 4 + vr * VSTR2 * 4 + vc * 16),
             vp + (size_t)vr * (SEQ / 2) * 4 + vc * 16);
    }
    CP_COMMIT();
}

// K -> fp16 elementwise; V -> fp16 transposed pair-words via smem tile.
__global__ void __launch_bounds__(256)
cvt_kv(const float* __restrict__ k, const float* __restrict__ v) {
    const int tid = threadIdx.x;
    const size_t nkw = (size_t)BATCH * SEQ * DIM / 2;
    for (size_t w = (size_t)blockIdx.x * 256 + tid; w < nkw; w += (size_t)gridDim.x * 256) {
        float2 kf = ((const float2*)k)[w];
        ((uint32_t*)g_kh)[w] = h2(kf.x, kf.y);
    }
    __shared__ float s[64][33];
    const int bx = blockIdx.x;
    const int b  = bx >> 7;
    const int pt = (bx >> 2) & 31;
    const int dt = bx & 3;
    const float* vb = v + ((size_t)b * SEQ + pt * 64) * DIM + dt * 32;
#pragma unroll
    for (int j = 0; j < 8; j++) {
        int i = tid + j * 256;
        int kk = i >> 5, dd = i & 31;
        s[kk][dd] = vb[(size_t)kk * DIM + dd];
    }
    __syncthreads();
    uint32_t* dst = g_vh + (size_t)b * DIM * (SEQ / 2) + (size_t)(dt * 32) * (SEQ / 2) + pt * 32;
#pragma unroll
    for (int j = 0; j < 4; j++) {
        int i = tid + j * 256;
        int pp = i & 31, dd = i >> 5;
        dst[(size_t)dd * (SEQ / 2) + pp] = h2(s[2 * pp][dd], s[2 * pp + 1][dd]);
    }
}

__global__ void __launch_bounds__(256, 1)
attn1(const float* __restrict__ qg_, float* __restrict__ out) {
    extern __shared__ float sm[];
    const uint32_t smb = smem_u32(sm);

    const int tid = threadIdx.x;
    const int warp = tid >> 5, lane = tid & 31;
    const int g = lane >> 2, qq = lane & 3;
    const int row0 = warp * 16 + g;

    const int b = blockIdx.y, qb = blockIdx.x;
    const float* qg = qg_ + ((size_t)b * SEQ + (size_t)qb * 128) * DIM;
    const __half* kh = g_kh + (size_t)b * SEQ * DIM;
    const uint32_t* vh = g_vh + (size_t)b * DIM * (SEQ / 2);
    float* ctx = out + ((size_t)b * SEQ + (size_t)qb * 128) * DIM;
    float* att = out + (size_t)BATCH * SEQ * DIM
                     + ((size_t)b * SEQ + (size_t)qb * 128) * SEQ;

    issue_k_grp128(smb, kh, 0, tid);
    issue_k_grp128(smb, kh, 1, tid);

    // Q fp16 A-frags (scale*log2e folded)
    const float qsc = 0.088388347648318447f * 1.4426950408889634f;
    const float* q0 = qg + (size_t)row0 * DIM;
    const float* q1 = q0 + 8 * DIM;
    uint32_t qa[8][4];
#pragma unroll
    for (int t = 0; t < 8; t++) {
        int c0 = 16 * t + 2 * qq;
        qa[t][0] = h2(q0[c0] * qsc,     q0[c0 + 1] * qsc);
        qa[t][1] = h2(q1[c0] * qsc,     q1[c0 + 1] * qsc);
        qa[t][2] = h2(q0[c0 + 8] * qsc, q0[c0 + 9] * qsc);
        qa[t][3] = h2(q1[c0 + 8] * qsc, q1[c0 + 9] * qsc);
    }

    const uint32_t kln = (uint32_t)((lane & 7) * KSTR * 4 + 16 * (lane >> 3));
    const uint32_t vln = (uint32_t)((lane & 7) * VSTR2 * 4 + ((lane >> 3) & 1) * 16
                                    + (lane >> 4) * 8 * VSTR2 * 4);

    // ============ PASS 1: row sums; 128-key groups, 3-slot ring ============
    float l0 = 0.f, l1 = 0.f;
    for (int t = 0; t < 16; ++t) {
        if (t < 15) { CP_WAIT(1); } else { CP_WAIT(0); }
        __syncthreads();
        if (t + 2 < 16) issue_k_grp128(smb, kh, t + 2, tid);

        const uint32_t slotb = smb + (uint32_t)((t % 3) * 2 * KBUF) * 4;
#pragma unroll
        for (int h = 0; h < 2; h++) {
            const uint32_t kbase = slotb + (uint32_t)(h * KBUF * 4) + kln;
            float cf[8][4];
#pragma unroll
            for (int i = 0; i < 8; i++) { cf[i][0] = cf[i][1] = cf[i][2] = cf[i][3] = 0.f; }
#pragma unroll
            for (int u = 0; u < 4; u++) {
#pragma unroll
                for (int nt = 0; nt < 8; nt++) {
                    uint32_t b00, b01, b10, b11;
                    ldsm4(b00, b01, b10, b11, kbase + (uint32_t)(nt * 8 * KSTR * 4 + u * 64));
                    mma_f16(cf[nt][0], cf[nt][1], cf[nt][2], cf[nt][3],
                            qa[2*u][0], qa[2*u][1], qa[2*u][2], qa[2*u][3], b00, b01);
                    mma_f16(cf[nt][0], cf[nt][1], cf[nt][2], cf[nt][3],
                            qa[2*u+1][0], qa[2*u+1][1], qa[2*u+1][2], qa[2*u+1][3], b10, b11);
                }
            }
#pragma unroll
            for (int nt = 0; nt < 8; nt++) {
                l0 += ex2(cf[nt][0]) + ex2(cf[nt][1]);
                l1 += ex2(cf[nt][2]) + ex2(cf[nt][3]);
            }
        }
    }

    l0 += __shfl_xor_sync(0xffffffffu, l0, 1);
    l0 += __shfl_xor_sync(0xffffffffu, l0, 2);
    l1 += __shfl_xor_sync(0xffffffffu, l1, 1);
    l1 += __shfl_xor_sync(0xffffffffu, l1, 2);
    const float r0 = 1.0f / l0;
    const float r1 = 1.0f / l1;

    // ================= PASS 2: normalized store + PV =================
    __syncthreads();                 // pass-1 buffer reads done everywhere
    issue_stage(smb, kh, vh, 0, tid);
    issue_stage(smb, kh, vh, 1, tid);
    issue_stage(smb, kh, vh, 2, tid);

    float o[16][4];
#pragma unroll
    for (int i = 0; i < 16; i++) { o[i][0] = o[i][1] = o[i][2] = o[i][3] = 0.f; }

    for (int s = 0; s < 32; ++s) {
        if (s <= 28) { CP_WAIT(2); } else { CP_WAIT(0); }
        __syncthreads();
        if (s <= 28) issue_stage(smb, kh, vh, s + 3, tid);

        const uint32_t kbase = smb + (uint32_t)((s & (NBUF - 1)) * STAGE_W) * 4 + kln;
        const uint32_t vbase = smb + (uint32_t)((s & (NBUF - 1)) * STAGE_W + KBUF) * 4 + vln;

        // ---- S = Q K^T (bit-identical to pass 1) ----
        float cf[8][4];
#pragma unroll
        for (int i = 0; i < 8; i++) { cf[i][0] = cf[i][1] = cf[i][2] = cf[i][3] = 0.f; }
#pragma unroll
        for (int u = 0; u < 4; u++) {
#pragma unroll
            for (int nt = 0; nt < 8; nt++) {
                uint32_t b00, b01, b10, b11;
                ldsm4(b00, b01, b10, b11, kbase + (uint32_t)(nt * 8 * KSTR * 4 + u * 64));
                mma_f16(cf[nt][0], cf[nt][1], cf[nt][2], cf[nt][3],
                        qa[2*u][0], qa[2*u][1], qa[2*u][2], qa[2*u][3], b00, b01);
                mma_f16(cf[nt][0], cf[nt][1], cf[nt][2], cf[nt][3],
                        qa[2*u+1][0], qa[2*u+1][1], qa[2*u+1][2], qa[2*u+1][3], b10, b11);
            }
        }

        // ---- p_norm = exp2(S) * rinv -> FINAL attention store ----
        float* a0p = att + (size_t)row0 * SEQ + 64 * s + 2 * qq;
        float* a1p = a0p + (size_t)8 * SEQ;
#pragma unroll
        for (int nt = 0; nt < 8; nt++) {
            float p0 = ex2(cf[nt][0]) * r0;
            float p1 = ex2(cf[nt][1]) * r0;
            float p2 = ex2(cf[nt][2]) * r1;
            float p3 = ex2(cf[nt][3]) * r1;
            *(float2*)(a0p + 8 * nt) = make_float2(p0, p1);
            *(float2*)(a1p + 8 * nt) = make_float2(p2, p3);
            cf[nt][0] = p0 * 64.0f; cf[nt][1] = p1 * 64.0f;   // x64 for fp16 range
            cf[nt][2] = p2 * 64.0f; cf[nt][3] = p3 * 64.0f;
        }

        // ---- O += (64*P_norm) V ----
#pragma unroll
        for (int tt = 0; tt < 4; tt++) {
            uint32_t A0 = h2(cf[2*tt][0],   cf[2*tt][1]);
            uint32_t A1 = h2(cf[2*tt][2],   cf[2*tt][3]);
            uint32_t A2 = h2(cf[2*tt+1][0], cf[2*tt+1][1]);
            uint32_t A3 = h2(cf[2*tt+1][2], cf[2*tt+1][3]);
#pragma unroll
            for (int ndp = 0; ndp < 8; ndp++) {
                uint32_t v00, v01, v10, v11;
                ldsm4(v00, v01, v10, v11, vbase + (uint32_t)(tt * 32 + ndp * 16 * VSTR2 * 4));
                mma_f16(o[2*ndp][0], o[2*ndp][1], o[2*ndp][2], o[2*ndp][3],
                        A0, A1, A2, A3, v00, v01);
                mma_f16(o[2*ndp+1][0], o[2*ndp+1][1], o[2*ndp+1][2], o[2*ndp+1][3],
                        A0, A1, A2, A3, v10, v11);
            }
        }
    }

    // ---- context = O / 64 ----
    const float inv64 = 0.015625f;
    float* c0p = ctx + (size_t)row0 * DIM + 2 * qq;
    float* c1p = c0p + (size_t)8 * DIM;
#pragma unroll
    for (int nd = 0; nd < 16; nd++) {
        *(float2*)(c0p + 8 * nd) = make_float2(o[nd][0] * inv64, o[nd][1] * inv64);
        *(float2*)(c1p + 8 * nd) = make_float2(o[nd][2] * inv64, o[nd][3] * inv64);
    }
}

__global__ void _noop() {}

extern "C" void kernel_launch(void* const* d_in, const int* in_sizes, int n_in,
                              void* d_out, int out_size) {
    const float* q = (const float*)d_in[0];
    const float* k = (const float*)d_in[1];
    const float* v = (const float*)d_in[2];
    float* out = (float*)d_out;

    cudaFuncSetAttribute(attn1, cudaFuncAttributeMaxDynamicSharedMemorySize,
                         SMEM_WORDS * 4);

    cvt_kv<<<2048, 256>>>(k, v);

    // keep the 4th launch = attn1 (ncu profile position)
    _noop<<<1, 32>>>();
    _noop<<<1, 32>>>();

    dim3 grid(SEQ / 128, BATCH);
    attn1<<<grid, 256, SMEM_WORDS * 4>>>(q, out);
}

// round 12
// speedup vs baseline: 1.2487x; 1.0654x over previous
#include <cuda_runtime.h>
#include <cuda_fp16.h>
#include <cstdint>
#include <cstddef>

// ScaledDotProductAttention B=16, S=2048, D=128 fp32 (sm_100 classic mma.sync).
// Out = context [16,2048,128] ++ attention [16,2048,2048].
//
// Round 12: two-pass, but pass 2 no longer recomputes QK.
//  Pass 1: K-only QK (128-key groups, 3-slot ring), p=exp2(S); row sums l,
//          AND p stored as fp16 to global scratch g_ph (st.global.cg).
//  Pass 2: cp.async P tiles from g_ph + V tiles; LDSM P directly as PV
//          A-frags; attention = unpack(P)*rinv (fp32 STG); O += P V;
//          context = O*rinv. QK MMAs + exp + packs all deleted from pass 2.
//  cvt_kv : K -> fp16 [b][key][d]; V -> fp16 transposed pair-words.

#define BATCH 16
#define SEQ   2048
#define DIM   128

#define KSTR  68                  // words per K row (64+4)  [pass 1]
#define VSTR2 36                  // words per V d-row (32+4)
#define PSTR  36                  // words per P q-row (32+4)
#define KBUF (64*KSTR)            // 4352
#define VBUF (128*VSTR2)          // 4608
#define PBUF (128*PSTR)           // 4608
#define STAGE_W (PBUF + VBUF)     // 9216 words  [pass 2 stage]
#define NBUF 4
#define SMEM_WORDS (NBUF * STAGE_W)   // 36864 words = 147,456 B
// pass-1 ring: 3 slots x 2*KBUF = 26112 words, aliases the same region

__device__ __half   g_kh[BATCH * SEQ * DIM];
__device__ uint32_t g_vh[BATCH * DIM * (SEQ / 2)];     // [b][d][pair]
__device__ uint32_t g_ph[(size_t)BATCH * SEQ * SEQ / 2]; // p fp16 pairs [row][key]

__device__ __forceinline__ uint32_t smem_u32(const void* p) {
    uint32_t a;
    asm("{ .reg .u64 t; cvta.to.shared.u64 t, %1; cvt.u32.u64 %0, t; }" : "=r"(a) : "l"(p));
    return a;
}
__device__ __forceinline__ float ex2(float x) {
    float y; asm("ex2.approx.f32 %0, %1;" : "=f"(y) : "f"(x)); return y;
}
__device__ __forceinline__ uint32_t h2(float a, float b) {
    uint32_t r;
    asm("cvt.rn.f16x2.f32 %0, %2, %1;" : "=r"(r) : "f"(a), "f"(b));
    return r;
}
__device__ __forceinline__ float2 h22f2(uint32_t u) {
    __half2 h = *(__half2*)&u;
    return __half22float2(h);
}
__device__ __forceinline__ void stcg(uint32_t* p, uint32_t v) {
    asm volatile("st.global.cg.u32 [%0], %1;" :: "l"(p), "r"(v));
}
__device__ __forceinline__ void mma_f16(float& c0, float& c1, float& c2, float& c3,
                                        uint32_t a0, uint32_t a1, uint32_t a2, uint32_t a3,
                                        uint32_t b0, uint32_t b1) {
    asm("mma.sync.aligned.m16n8k16.row.col.f32.f16.f16.f32 "
        "{%0,%1,%2,%3}, {%4,%5,%6,%7}, {%8,%9}, {%0,%1,%2,%3};"
        : "+f"(c0), "+f"(c1), "+f"(c2), "+f"(c3)
        : "r"(a0), "r"(a1), "r"(a2), "r"(a3), "r"(b0), "r"(b1));
}
__device__ __forceinline__ void ldsm4(uint32_t& r0, uint32_t& r1, uint32_t& r2,
                                      uint32_t& r3, uint32_t addr) {
    asm volatile("ldmatrix.sync.aligned.m8n8.x4.shared.b16 {%0,%1,%2,%3}, [%4];"
                 : "=r"(r0), "=r"(r1), "=r"(r2), "=r"(r3) : "r"(addr));
}

#define CP16(dst, src) \
    asm volatile("cp.async.cg.shared.global [%0], [%1], 16;" :: "r"(dst), "l"(src))
#define CP_COMMIT() asm volatile("cp.async.commit_group;" ::: "memory")
#define CP_WAIT(n)  asm volatile("cp.async.wait_group %0;" :: "n"(n) : "memory")

// pass-1 group fill: 128 keys of K into slot grp%3. 256 threads.
__device__ __forceinline__ void issue_k_grp128(uint32_t smb, const __half* kh,
                                               int grp, int tid) {
    const uint32_t base = smb + (uint32_t)((grp % 3) * 2 * KBUF) * 4;
    const char* kp = (const char*)(kh + (size_t)grp * 128 * DIM);
#pragma unroll
    for (int j = 0; j < 8; j++) {
        int i = tid + j * 256;
        int kr = i >> 4, kc = i & 15;
        uint32_t off = (uint32_t)(((kr >> 6) * KBUF + (kr & 63) * KSTR) * 4 + kc * 16);
        CP16(base + off, kp + kr * 256 + kc * 16);
    }
    CP_COMMIT();
}

// pass-2 stage: P 128 q-rows x 128B slice + V 128 d-rows x 128B slice.
__device__ __forceinline__ void issue_stage2(uint32_t smb, const char* php,
                                             const uint32_t* vh, int s, int tid) {
    const uint32_t base = smb + (uint32_t)((s & (NBUF - 1)) * STAGE_W) * 4;
    const char* pp = php + (size_t)s * 128;               // row stride 4KB
    const char* vp = (const char*)(vh + (size_t)s * 32);  // row stride 4KB
#pragma unroll
    for (int j = 0; j < 4; j++) {
        int i = tid + j * 256;
        int r = i >> 3, c = i & 7;           // 128 rows x 8 chunks
        CP16(base + (uint32_t)(r * PSTR * 4 + c * 16), pp + (size_t)r * 4096 + c * 16);
        CP16(base + (uint32_t)(PBUF * 4 + r * VSTR2 * 4 + c * 16),
             vp + (size_t)r * (SEQ / 2) * 4 + c * 16);
    }
    CP_COMMIT();
}

// K -> fp16 elementwise; V -> fp16 transposed pair-words via smem tile.
__global__ void __launch_bounds__(256)
cvt_kv(const float* __restrict__ k, const float* __restrict__ v) {
    const int tid = threadIdx.x;
    const size_t nkw = (size_t)BATCH * SEQ * DIM / 2;
    for (size_t w = (size_t)blockIdx.x * 256 + tid; w < nkw; w += (size_t)gridDim.x * 256) {
        float2 kf = ((const float2*)k)[w];
        ((uint32_t*)g_kh)[w] = h2(kf.x, kf.y);
    }
    __shared__ float s[64][33];
    const int bx = blockIdx.x;
    const int b  = bx >> 7;
    const int pt = (bx >> 2) & 31;
    const int dt = bx & 3;
    const float* vb = v + ((size_t)b * SEQ + pt * 64) * DIM + dt * 32;
#pragma unroll
    for (int j = 0; j < 8; j++) {
        int i = tid + j * 256;
        int kk = i >> 5, dd = i & 31;
        s[kk][dd] = vb[(size_t)kk * DIM + dd];
    }
    __syncthreads();
    uint32_t* dst = g_vh + (size_t)b * DIM * (SEQ / 2) + (size_t)(dt * 32) * (SEQ / 2) + pt * 32;
#pragma unroll
    for (int j = 0; j < 4; j++) {
        int i = tid + j * 256;
        int pp = i & 31, dd = i >> 5;
        dst[(size_t)dd * (SEQ / 2) + pp] = h2(s[2 * pp][dd], s[2 * pp + 1][dd]);
    }
}

__global__ void __launch_bounds__(256, 1)
attn1(const float* __restrict__ qg_, float* __restrict__ out) {
    extern __shared__ float sm[];
    const uint32_t smb = smem_u32(sm);

    const int tid = threadIdx.x;
    const int warp = tid >> 5, lane = tid & 31;
    const int g = lane >> 2, qq = lane & 3;
    const int row0 = warp * 16 + g;

    const int b = blockIdx.y, qb = blockIdx.x;
    const size_t R0 = (size_t)b * SEQ + (size_t)qb * 128;   // first global row
    const float* qg = qg_ + R0 * DIM;
    const __half* kh = g_kh + (size_t)b * SEQ * DIM;
    const uint32_t* vh = g_vh + (size_t)b * DIM * (SEQ / 2);
    float* ctx = out + R0 * DIM;
    float* att = out + (size_t)BATCH * SEQ * DIM + R0 * SEQ;

    issue_k_grp128(smb, kh, 0, tid);
    issue_k_grp128(smb, kh, 1, tid);

    // Q fp16 A-frags (scale*log2e folded)
    const float qsc = 0.088388347648318447f * 1.4426950408889634f;
    const float* q0 = qg + (size_t)row0 * DIM;
    const float* q1 = q0 + 8 * DIM;
    uint32_t qa[8][4];
#pragma unroll
    for (int t = 0; t < 8; t++) {
        int c0 = 16 * t + 2 * qq;
        qa[t][0] = h2(q0[c0] * qsc,     q0[c0 + 1] * qsc);
        qa[t][1] = h2(q1[c0] * qsc,     q1[c0 + 1] * qsc);
        qa[t][2] = h2(q0[c0 + 8] * qsc, q0[c0 + 9] * qsc);
        qa[t][3] = h2(q1[c0 + 8] * qsc, q1[c0 + 9] * qsc);
    }

    const uint32_t kln = (uint32_t)((lane & 7) * KSTR * 4 + 16 * (lane >> 3));
    const uint32_t vln = (uint32_t)((lane & 7) * VSTR2 * 4 + ((lane >> 3) & 1) * 16
                                    + (lane >> 4) * 8 * VSTR2 * 4);
    // P A-frag LDSM addressing (proven round-10 Q mapping)
    const uint32_t pln = (uint32_t)((16 * warp + (lane & 15)) * PSTR * 4
                                    + (lane >> 4) * 16);

    // ============ PASS 1: row sums + p fp16 -> g_ph ============
    uint32_t* pr0b = g_ph + (R0 + row0) * (SEQ / 2) + qq;     // uint32 index
    float l0 = 0.f, l1 = 0.f;
    for (int t = 0; t < 16; ++t) {
        if (t < 15) { CP_WAIT(1); } else { CP_WAIT(0); }
        __syncthreads();
        if (t + 2 < 16) issue_k_grp128(smb, kh, t + 2, tid);

        const uint32_t slotb = smb + (uint32_t)((t % 3) * 2 * KBUF) * 4;
#pragma unroll
        for (int h = 0; h < 2; h++) {
            const uint32_t kbase = slotb + (uint32_t)(h * KBUF * 4) + kln;
            float cf[8][4];
#pragma unroll
            for (int i = 0; i < 8; i++) { cf[i][0] = cf[i][1] = cf[i][2] = cf[i][3] = 0.f; }
#pragma unroll
            for (int u = 0; u < 4; u++) {
#pragma unroll
                for (int nt = 0; nt < 8; nt++) {
                    uint32_t b00, b01, b10, b11;
                    ldsm4(b00, b01, b10, b11, kbase + (uint32_t)(nt * 8 * KSTR * 4 + u * 64));
                    mma_f16(cf[nt][0], cf[nt][1], cf[nt][2], cf[nt][3],
                            qa[2*u][0], qa[2*u][1], qa[2*u][2], qa[2*u][3], b00, b01);
                    mma_f16(cf[nt][0], cf[nt][1], cf[nt][2], cf[nt][3],
                            qa[2*u+1][0], qa[2*u+1][1], qa[2*u+1][2], qa[2*u+1][3], b10, b11);
                }
            }
            uint32_t* pr0 = pr0b + t * 64 + h * 32;           // cols 128t+64h+2qq
            uint32_t* pr1 = pr0 + 8 * (SEQ / 2);
#pragma unroll
            for (int nt = 0; nt < 8; nt++) {
                float p0 = ex2(cf[nt][0]);
                float p1 = ex2(cf[nt][1]);
                float p2 = ex2(cf[nt][2]);
                float p3 = ex2(cf[nt][3]);
                l0 += p0 + p1; l1 += p2 + p3;
                stcg(pr0 + 4 * nt, h2(p0, p1));
                stcg(pr1 + 4 * nt, h2(p2, p3));
            }
        }
    }

    l0 += __shfl_xor_sync(0xffffffffu, l0, 1);
    l0 += __shfl_xor_sync(0xffffffffu, l0, 2);
    l1 += __shfl_xor_sync(0xffffffffu, l1, 1);
    l1 += __shfl_xor_sync(0xffffffffu, l1, 2);
    const float r0 = 1.0f / l0;
    const float r1 = 1.0f / l1;

    // ================= PASS 2: P/V stream, PV + normalized stores ==========
    __syncthreads();                 // pass-1 smem reads done + g_ph ordered
    const char* php = (const char*)(g_ph + R0 * (SEQ / 2));
    issue_stage2(smb, php, vh, 0, tid);
    issue_stage2(smb, php, vh, 1, tid);
    issue_stage2(smb, php, vh, 2, tid);

    float o[16][4];
#pragma unroll
    for (int i = 0; i < 16; i++) { o[i][0] = o[i][1] = o[i][2] = o[i][3] = 0.f; }

    for (int s = 0; s < 32; ++s) {
        if (s <= 28) { CP_WAIT(2); } else { CP_WAIT(0); }
        __syncthreads();
        if (s <= 28) issue_stage2(smb, php, vh, s + 3, tid);

        const uint32_t pbase = smb + (uint32_t)((s & (NBUF - 1)) * STAGE_W) * 4 + pln;
        const uint32_t vbase = smb + (uint32_t)((s & (NBUF - 1)) * STAGE_W + PBUF) * 4 + vln;

        // ---- LDSM P as A-frags (16 regs = this warp's 16 rows x 64 keys) ----
        uint32_t A[4][4];
#pragma unroll
        for (int tt = 0; tt < 4; tt++)
            ldsm4(A[tt][0], A[tt][1], A[tt][2], A[tt][3], pbase + (uint32_t)(tt * 32));

        // ---- attention = p * rinv (fp32) ----
        float* a0p = att + (size_t)row0 * SEQ + 64 * s + 2 * qq;
        float* a1p = a0p + (size_t)8 * SEQ;
#pragma unroll
        for (int tt = 0; tt < 4; tt++) {
            float2 x0 = h22f2(A[tt][0]);
            float2 x1 = h22f2(A[tt][1]);
            float2 x2 = h22f2(A[tt][2]);
            float2 x3 = h22f2(A[tt][3]);
            *(float2*)(a0p + 16 * tt)     = make_float2(x0.x * r0, x0.y * r0);
            *(float2*)(a0p + 16 * tt + 8) = make_float2(x2.x * r0, x2.y * r0);
            *(float2*)(a1p + 16 * tt)     = make_float2(x1.x * r1, x1.y * r1);
            *(float2*)(a1p + 16 * tt + 8) = make_float2(x3.x * r1, x3.y * r1);
        }

        // ---- O += P V ----
#pragma unroll
        for (int tt = 0; tt < 4; tt++) {
#pragma unroll
            for (int ndp = 0; ndp < 8; ndp++) {
                uint32_t v00, v01, v10, v11;
                ldsm4(v00, v01, v10, v11, vbase + (uint32_t)(tt * 32 + ndp * 16 * VSTR2 * 4));
                mma_f16(o[2*ndp][0], o[2*ndp][1], o[2*ndp][2], o[2*ndp][3],
                        A[tt][0], A[tt][1], A[tt][2], A[tt][3], v00, v01);
                mma_f16(o[2*ndp+1][0], o[2*ndp+1][1], o[2*ndp+1][2], o[2*ndp+1][3],
                        A[tt][0], A[tt][1], A[tt][2], A[tt][3], v10, v11);
            }
        }
    }

    // ---- context = O * rinv ----
    float* c0p = ctx + (size_t)row0 * DIM + 2 * qq;
    float* c1p = c0p + (size_t)8 * DIM;
#pragma unroll
    for (int nd = 0; nd < 16; nd++) {
        *(float2*)(c0p + 8 * nd) = make_float2(o[nd][0] * r0, o[nd][1] * r0);
        *(float2*)(c1p + 8 * nd) = make_float2(o[nd][2] * r1, o[nd][3] * r1);
    }
}

__global__ void _noop() {}

extern "C" void kernel_launch(void* const* d_in, const int* in_sizes, int n_in,
                              void* d_out, int out_size) {
    const float* q = (const float*)d_in[0];
    const float* k = (const float*)d_in[1];
    const float* v = (const float*)d_in[2];
    float* out = (float*)d_out;

    cudaFuncSetAttribute(attn1, cudaFuncAttributeMaxDynamicSharedMemorySize,
                         SMEM_WORDS * 4);

    cvt_kv<<<2048, 256>>>(k, v);

    // keep the 4th launch = attn1 (ncu profile position)
    _noop<<<1, 32>>>();
    _noop<<<1, 32>>>();

    dim3 grid(SEQ / 128, BATCH);
    attn1<<<grid, 256, SMEM_WORDS * 4>>>(q, out);
}